// round 7
// baseline (speedup 1.0000x reference)
#include <cuda_runtime.h>

#define MAX_N 100000
#define MAX_E 1200000
#define FDIM 64

__device__ float g_Q[(size_t)MAX_N * FDIM];      // Q = X@W1 + (X*X)@W2
__device__ int   g_cnt[MAX_N];                   // per-row edge count
__device__ int   g_rowstart[MAX_N];              // exclusive scan of g_cnt
__device__ int   g_cursor[MAX_N];                // scatter cursor (== row end after)
__device__ int2  g_edges[MAX_E];                 // binned (col, val) per row
__device__ int   g_bsum[128];                    // per-block totals
__device__ int   g_bar;                          // spin-barrier counter (memset 0)

// ---- packed f32x2 helpers (sm_103a FFMA2: 2 fp32 FMAs / issue slot) ----
typedef unsigned long long u64;
__device__ __forceinline__ u64 pack2(float lo, float hi) {
    u64 r; asm("mov.b64 %0, {%1, %2};" : "=l"(r) : "f"(lo), "f"(hi)); return r;
}
__device__ __forceinline__ void unpack2(u64 p, float& lo, float& hi) {
    asm("mov.b64 {%0, %1}, %2;" : "=f"(lo), "=f"(hi) : "l"(p));
}
__device__ __forceinline__ u64 fma2(u64 a, u64 b, u64 c) {
    u64 d; asm("fma.rn.f32x2 %0, %1, %2, %3;" : "=l"(d) : "l"(a), "l"(b), "l"(c)); return d;
}
__device__ __forceinline__ u64 mul2(u64 a, u64 b) {
    u64 d; asm("mul.rn.f32x2 %0, %1, %2;" : "=l"(d) : "l"(a), "l"(b)); return d;
}

// ---------------------------------------------------------------------------
// Dense GEMM (f32x2-packed) + fused edge histogram. (identical to R6)
// ---------------------------------------------------------------------------
__global__ __launch_bounds__(256) void gnn_dense_hist(
    const float* __restrict__ X,
    const float* __restrict__ W1, const float* __restrict__ b1,
    const float* __restrict__ W2, const float* __restrict__ b2,
    const int* __restrict__ rows,
    float* __restrict__ out, int N, int E)
{
    extern __shared__ float smem[];
    float* W1s = smem;          // 64*64
    float* W2s = smem + 4096;   // 64*64
    float* Xs  = smem + 8192;   // 128*64

    const int tid = threadIdx.x;

    #pragma unroll
    for (int i = tid; i < 1024; i += 256) {
        reinterpret_cast<float4*>(W1s)[i] = reinterpret_cast<const float4*>(W1)[i];
        reinterpret_cast<float4*>(W2s)[i] = reinterpret_cast<const float4*>(W2)[i];
    }

    const int row0 = blockIdx.x * 128;
    #pragma unroll
    for (int i = tid; i < 128 * 16; i += 256) {
        const int r  = i >> 4;
        const int gr = row0 + r;
        float4 v = make_float4(0.f, 0.f, 0.f, 0.f);
        if (gr < N) v = reinterpret_cast<const float4*>(X)[(size_t)gr * 16 + (i & 15)];
        reinterpret_cast<float4*>(Xs)[i] = v;
    }

    // Fused histogram: spread-address int REDG, hidden under the FFMA2 loop.
    const int stride = gridDim.x * 256;
    for (int e = blockIdx.x * 256 + tid; e < E; e += stride)
        atomicAdd(&g_cnt[__ldg(rows + e)], 1);

    __syncthreads();

    const int rg  = (tid >> 4) * 8;
    const int cg4 = tid & 15;

    const u64* W1p = reinterpret_cast<const u64*>(W1s);
    const u64* W2p = reinterpret_cast<const u64*>(W2s);

    u64 acc1a[8], acc1b[8], acc2a[8], acc2b[8];
    #pragma unroll
    for (int i = 0; i < 8; ++i) { acc1a[i]=0; acc1b[i]=0; acc2a[i]=0; acc2b[i]=0; }

    #pragma unroll 4
    for (int k = 0; k < 64; ++k) {
        const u64 w1a = W1p[k * 32 + 2 * cg4];
        const u64 w1b = W1p[k * 32 + 2 * cg4 + 1];
        const u64 w2a = W2p[k * 32 + 2 * cg4];
        const u64 w2b = W2p[k * 32 + 2 * cg4 + 1];
        #pragma unroll
        for (int i = 0; i < 8; ++i) {
            const float x  = Xs[(rg + i) * 64 + k];
            const u64 xp  = pack2(x, x);
            const u64 xsq = mul2(xp, xp);
            acc1a[i] = fma2(xp,  w1a, acc1a[i]);
            acc1b[i] = fma2(xp,  w1b, acc1b[i]);
            acc2a[i] = fma2(xsq, w2a, acc2a[i]);
            acc2b[i] = fma2(xsq, w2b, acc2b[i]);
        }
    }

    const int cc = cg4 * 4;
    float4 bb;
    bb.x = __ldg(b1 + cc + 0) + __ldg(b2 + cc + 0);
    bb.y = __ldg(b1 + cc + 1) + __ldg(b2 + cc + 1);
    bb.z = __ldg(b1 + cc + 2) + __ldg(b2 + cc + 2);
    bb.w = __ldg(b1 + cc + 3) + __ldg(b2 + cc + 3);

    #pragma unroll
    for (int i = 0; i < 8; ++i) {
        const int gr = row0 + rg + i;
        if (gr < N) {
            float a10, a11, a12, a13, a20, a21, a22, a23;
            unpack2(acc1a[i], a10, a11);
            unpack2(acc1b[i], a12, a13);
            unpack2(acc2a[i], a20, a21);
            unpack2(acc2b[i], a22, a23);
            float4 o, q;
            o.x = a10 + bb.x;  q.x = a10 + a20;
            o.y = a11 + bb.y;  q.y = a11 + a21;
            o.z = a12 + bb.z;  q.z = a12 + a22;
            o.w = a13 + bb.w;  q.w = a13 + a23;
            reinterpret_cast<float4*>(out)[(size_t)gr * 16 + cg4] = o;
            reinterpret_cast<float4*>(g_Q)[(size_t)gr * 16 + cg4] = q;
        }
    }
}

// Spin barrier among nb co-resident blocks (nb <= 148: all wave-1 resident).
__device__ __forceinline__ void coop_barrier(int target) {
    __syncthreads();
    if (threadIdx.x == 0) {
        __threadfence();
        atomicAdd(&g_bar, 1);
        while (*(volatile int*)&g_bar < target) { }
    }
    __syncthreads();
}

// ---------------------------------------------------------------------------
// ONE build kernel: exclusive scan of g_cnt -> rowstart/cursor, then scatter.
// nb blocks x 1024 threads (nb=98 -> co-resident; spin barriers safe).
// ---------------------------------------------------------------------------
__global__ __launch_bounds__(1024) void gnn_build(
    const int* __restrict__ rows,
    const int* __restrict__ cols,
    const float* __restrict__ vals, int N, int E, int nb)
{
    __shared__ int ws[32];
    __shared__ int s_pfx;

    const int bid = blockIdx.x, tid = threadIdx.x;
    const int lane = tid & 31, wid = tid >> 5;
    const int i = bid * 1024 + tid;
    const int v = (i < N) ? g_cnt[i] : 0;

    // Block-local exclusive scan
    int incl = v;
    #pragma unroll
    for (int off = 1; off < 32; off <<= 1) {
        int u = __shfl_up_sync(0xffffffffu, incl, off);
        if (lane >= off) incl += u;
    }
    if (lane == 31) ws[wid] = incl;
    __syncthreads();
    if (wid == 0) {
        int x = ws[lane];
        #pragma unroll
        for (int off = 1; off < 32; off <<= 1) {
            int u = __shfl_up_sync(0xffffffffu, x, off);
            if (lane >= off) x += u;
        }
        ws[lane] = x;
    }
    __syncthreads();
    const int excl = incl - v + (wid ? ws[wid - 1] : 0);

    if (tid == 1023) g_bsum[bid] = excl + v;      // block total
    coop_barrier(nb);

    // Each block sums its predecessors' totals (lane-parallel over <=98 ints).
    if (wid == 0) {
        int s = 0;
        for (int j = lane; j < bid; j += 32) s += __ldcg(g_bsum + j);
        #pragma unroll
        for (int off = 16; off > 0; off >>= 1)
            s += __shfl_down_sync(0xffffffffu, s, off);
        if (lane == 0) s_pfx = s;
    }
    __syncthreads();
    const int base = s_pfx;

    if (i < N) {
        const int ex = base + excl;
        g_rowstart[i] = ex;
        g_cursor[i]   = ex;
    }
    coop_barrier(2 * nb);

    // Scatter edges into row bins.
    const int stride = nb * 1024;
    for (int e = bid * 1024 + tid; e < E; e += stride) {
        const int r   = __ldg(rows + e);
        const int pos = atomicAdd(&g_cursor[r], 1);
        g_edges[pos] = make_int2(__ldg(cols + e), __float_as_int(__ldg(vals + e)));
    }
}

// ---------------------------------------------------------------------------
// CSR SpMM: 16 lanes per row, float4 per lane. (identical to R6)
// ---------------------------------------------------------------------------
__global__ __launch_bounds__(256) void gnn_spmm_csr(float* __restrict__ out, int N)
{
    const int gid = blockIdx.x * blockDim.x + threadIdx.x;
    const int row = gid >> 4;
    if (row >= N) return;
    const int lane16 = gid & 15;

    const int start = __ldg(g_rowstart + row);
    const int end   = __ldg(g_cursor + row);
    if (end <= start) return;

    const float4* __restrict__ Q4 = reinterpret_cast<const float4*>(g_Q);
    float4 acc = make_float4(0.f, 0.f, 0.f, 0.f);

    int j = start;
    for (; j + 3 < end; j += 4) {
        const int2 cv0 = __ldg(g_edges + j);
        const int2 cv1 = __ldg(g_edges + j + 1);
        const int2 cv2 = __ldg(g_edges + j + 2);
        const int2 cv3 = __ldg(g_edges + j + 3);
        const float4 q0 = __ldg(Q4 + (size_t)cv0.x * 16 + lane16);
        const float4 q1 = __ldg(Q4 + (size_t)cv1.x * 16 + lane16);
        const float4 q2 = __ldg(Q4 + (size_t)cv2.x * 16 + lane16);
        const float4 q3 = __ldg(Q4 + (size_t)cv3.x * 16 + lane16);
        const float v0 = __int_as_float(cv0.y);
        const float v1 = __int_as_float(cv1.y);
        const float v2 = __int_as_float(cv2.y);
        const float v3 = __int_as_float(cv3.y);
        acc.x = fmaf(v0, q0.x, acc.x); acc.y = fmaf(v0, q0.y, acc.y);
        acc.z = fmaf(v0, q0.z, acc.z); acc.w = fmaf(v0, q0.w, acc.w);
        acc.x = fmaf(v1, q1.x, acc.x); acc.y = fmaf(v1, q1.y, acc.y);
        acc.z = fmaf(v1, q1.z, acc.z); acc.w = fmaf(v1, q1.w, acc.w);
        acc.x = fmaf(v2, q2.x, acc.x); acc.y = fmaf(v2, q2.y, acc.y);
        acc.z = fmaf(v2, q2.z, acc.z); acc.w = fmaf(v2, q2.w, acc.w);
        acc.x = fmaf(v3, q3.x, acc.x); acc.y = fmaf(v3, q3.y, acc.y);
        acc.z = fmaf(v3, q3.z, acc.z); acc.w = fmaf(v3, q3.w, acc.w);
    }
    for (; j < end; ++j) {
        const int2 cv = __ldg(g_edges + j);
        const float4 q = __ldg(Q4 + (size_t)cv.x * 16 + lane16);
        const float v = __int_as_float(cv.y);
        acc.x = fmaf(v, q.x, acc.x); acc.y = fmaf(v, q.y, acc.y);
        acc.z = fmaf(v, q.z, acc.z); acc.w = fmaf(v, q.w, acc.w);
    }

    float4* orow = reinterpret_cast<float4*>(out) + (size_t)row * 16 + lane16;
    float4 o = *orow;
    o.x += acc.x; o.y += acc.y; o.z += acc.z; o.w += acc.w;
    *orow = o;
}

extern "C" void kernel_launch(void* const* d_in, const int* in_sizes, int n_in,
                              void* d_out, int out_size)
{
    const int*   rows = (const int*)  d_in[0];
    const int*   cols = (const int*)  d_in[1];
    const float* vals = (const float*)d_in[2];
    const float* X    = (const float*)d_in[3];
    const float* W1   = (const float*)d_in[4];
    const float* b1   = (const float*)d_in[5];
    const float* W2   = (const float*)d_in[6];
    const float* b2   = (const float*)d_in[7];
    float* out = (float*)d_out;

    const int E = in_sizes[0];
    const int N = in_sizes[3] / FDIM;
    const int nb = (N + 1023) / 1024;           // 98 (< 148, co-resident)

    cudaFuncSetAttribute(gnn_dense_hist, cudaFuncAttributeMaxDynamicSharedMemorySize, 65536);

    void* p = nullptr;
    cudaGetSymbolAddress(&p, g_cnt);
    cudaMemsetAsync(p, 0, (size_t)N * sizeof(int));
    cudaGetSymbolAddress(&p, g_bar);
    cudaMemsetAsync(p, 0, sizeof(int));

    const int blocksD = (N + 127) / 128;
    gnn_dense_hist<<<blocksD, 256, 65536>>>(X, W1, b1, W2, b2, rows, out, N, E);

    gnn_build<<<nb, 1024>>>(rows, cols, vals, N, E, nb);

    const long long work = (long long)N * 16;
    gnn_spmm_csr<<<(int)((work + 255) / 256), 256>>>(out, N);
}

// round 8
// speedup vs baseline: 1.0902x; 1.0902x over previous
#include <cuda_runtime.h>

#define MAX_N 100000
#define MAX_E 1200000
#define FDIM 64

__device__ float g_Q[(size_t)MAX_N * FDIM];      // Q = X@W1 + (X*X)@W2
__device__ int   g_cnt[MAX_N];                   // per-row edge count
__device__ int   g_rowstart[MAX_N];              // exclusive scan of g_cnt
__device__ int   g_cursor[MAX_N];                // scatter cursor (== row end after)
__device__ int2  g_edges[MAX_E];                 // binned (col, val) per row
__device__ int   g_bsum[128];                    // block sums for the scan

// ---- packed f32x2 helpers (sm_103a FFMA2: 2 fp32 FMAs / issue slot) ----
typedef unsigned long long u64;
__device__ __forceinline__ u64 pack2(float lo, float hi) {
    u64 r; asm("mov.b64 %0, {%1, %2};" : "=l"(r) : "f"(lo), "f"(hi)); return r;
}
__device__ __forceinline__ void unpack2(u64 p, float& lo, float& hi) {
    asm("mov.b64 {%0, %1}, %2;" : "=f"(lo), "=f"(hi) : "l"(p));
}
__device__ __forceinline__ u64 fma2(u64 a, u64 b, u64 c) {
    u64 d; asm("fma.rn.f32x2 %0, %1, %2, %3;" : "=l"(d) : "l"(a), "l"(b), "l"(c)); return d;
}
__device__ __forceinline__ u64 mul2(u64 a, u64 b) {
    u64 d; asm("mul.rn.f32x2 %0, %1, %2;" : "=l"(d) : "l"(a), "l"(b)); return d;
}

// ---------------------------------------------------------------------------
// Dense GEMM (f32x2) + fused histogram. 64-row tile, 4 rows/thread,
// 48KB smem, 3 blocks/SM target (R7 profile: issue-bound at 16 warps/SM).
// ---------------------------------------------------------------------------
__global__ __launch_bounds__(256, 3) void gnn_dense_hist(
    const float* __restrict__ X,
    const float* __restrict__ W1, const float* __restrict__ b1,
    const float* __restrict__ W2, const float* __restrict__ b2,
    const int* __restrict__ rows,
    float* __restrict__ out, int N, int E)
{
    extern __shared__ float smem[];
    float* W1s = smem;          // 64*64 = 16KB
    float* W2s = smem + 4096;   // 16KB
    float* Xs  = smem + 8192;   // 64*64 = 16KB

    const int tid = threadIdx.x;

    #pragma unroll
    for (int i = tid; i < 1024; i += 256) {
        reinterpret_cast<float4*>(W1s)[i] = reinterpret_cast<const float4*>(W1)[i];
        reinterpret_cast<float4*>(W2s)[i] = reinterpret_cast<const float4*>(W2)[i];
    }

    const int row0 = blockIdx.x * 64;
    #pragma unroll
    for (int i = tid; i < 64 * 16; i += 256) {
        const int r  = i >> 4;
        const int gr = row0 + r;
        float4 v = make_float4(0.f, 0.f, 0.f, 0.f);
        if (gr < N) v = reinterpret_cast<const float4*>(X)[(size_t)gr * 16 + (i & 15)];
        reinterpret_cast<float4*>(Xs)[i] = v;
    }

    // Fused histogram: spread-address int REDG, hidden under the FFMA2 loop.
    const int stride = gridDim.x * 256;
    for (int e = blockIdx.x * 256 + tid; e < E; e += stride)
        atomicAdd(&g_cnt[__ldg(rows + e)], 1);

    __syncthreads();

    const int rg  = (tid >> 4) * 4;    // 4 rows per thread
    const int cg4 = tid & 15;          // float4 column group

    const u64* W1p = reinterpret_cast<const u64*>(W1s);
    const u64* W2p = reinterpret_cast<const u64*>(W2s);

    u64 acc1a[4], acc1b[4], acc2a[4], acc2b[4];
    #pragma unroll
    for (int i = 0; i < 4; ++i) { acc1a[i]=0; acc1b[i]=0; acc2a[i]=0; acc2b[i]=0; }

    #pragma unroll 8
    for (int k = 0; k < 64; ++k) {
        const u64 w1a = W1p[k * 32 + 2 * cg4];
        const u64 w1b = W1p[k * 32 + 2 * cg4 + 1];
        const u64 w2a = W2p[k * 32 + 2 * cg4];
        const u64 w2b = W2p[k * 32 + 2 * cg4 + 1];
        #pragma unroll
        for (int i = 0; i < 4; ++i) {
            const float x  = Xs[(rg + i) * 64 + k];
            const u64 xp  = pack2(x, x);
            const u64 xsq = mul2(xp, xp);
            acc1a[i] = fma2(xp,  w1a, acc1a[i]);
            acc1b[i] = fma2(xp,  w1b, acc1b[i]);
            acc2a[i] = fma2(xsq, w2a, acc2a[i]);
            acc2b[i] = fma2(xsq, w2b, acc2b[i]);
        }
    }

    const int cc = cg4 * 4;
    float4 bb;
    bb.x = __ldg(b1 + cc + 0) + __ldg(b2 + cc + 0);
    bb.y = __ldg(b1 + cc + 1) + __ldg(b2 + cc + 1);
    bb.z = __ldg(b1 + cc + 2) + __ldg(b2 + cc + 2);
    bb.w = __ldg(b1 + cc + 3) + __ldg(b2 + cc + 3);

    #pragma unroll
    for (int i = 0; i < 4; ++i) {
        const int gr = row0 + rg + i;
        if (gr < N) {
            float a10, a11, a12, a13, a20, a21, a22, a23;
            unpack2(acc1a[i], a10, a11);
            unpack2(acc1b[i], a12, a13);
            unpack2(acc2a[i], a20, a21);
            unpack2(acc2b[i], a22, a23);
            float4 o, q;
            o.x = a10 + bb.x;  q.x = a10 + a20;
            o.y = a11 + bb.y;  q.y = a11 + a21;
            o.z = a12 + bb.z;  q.z = a12 + a22;
            o.w = a13 + bb.w;  q.w = a13 + a23;
            reinterpret_cast<float4*>(out)[(size_t)gr * 16 + cg4] = o;
            reinterpret_cast<float4*>(g_Q)[(size_t)gr * 16 + cg4] = q;
        }
    }
}

// ---------------------------------------------------------------------------
// Scan stage (R6 measured-best): exclusive scan of g_cnt -> rowstart/cursor
// ---------------------------------------------------------------------------
__device__ __forceinline__ int warp_incl_scan(int v) {
    #pragma unroll
    for (int off = 1; off < 32; off <<= 1) {
        int u = __shfl_up_sync(0xffffffffu, v, off);
        if ((threadIdx.x & 31) >= off) v += u;
    }
    return v;
}

__global__ __launch_bounds__(1024) void scan_blocksums(int N) {
    const int i = blockIdx.x * 1024 + threadIdx.x;
    int v = (i < N) ? g_cnt[i] : 0;
    #pragma unroll
    for (int off = 16; off > 0; off >>= 1)
        v += __shfl_down_sync(0xffffffffu, v, off);
    __shared__ int ws[32];
    const int lane = threadIdx.x & 31, wid = threadIdx.x >> 5;
    if (lane == 0) ws[wid] = v;
    __syncthreads();
    if (wid == 0) {
        int x = ws[lane];
        #pragma unroll
        for (int off = 16; off > 0; off >>= 1)
            x += __shfl_down_sync(0xffffffffu, x, off);
        if (lane == 0) g_bsum[blockIdx.x] = x;
    }
}

__global__ __launch_bounds__(128) void scan_bsums(int nb) {
    __shared__ int s[128];
    const int t = threadIdx.x;
    s[t] = (t < nb) ? g_bsum[t] : 0;
    __syncthreads();
    #pragma unroll
    for (int off = 1; off < 128; off <<= 1) {
        int v = (t >= off) ? s[t - off] : 0;
        __syncthreads();
        s[t] += v;
        __syncthreads();
    }
    if (t < nb) g_bsum[t] = s[t];
}

__global__ __launch_bounds__(1024) void scan_write(int N) {
    const int t = threadIdx.x, b = blockIdx.x;
    const int i = b * 1024 + t;
    const int v = (i < N) ? g_cnt[i] : 0;
    const int lane = t & 31, wid = t >> 5;
    int inc = warp_incl_scan(v);
    __shared__ int ws[32];
    if (lane == 31) ws[wid] = inc;
    __syncthreads();
    if (wid == 0) {
        int x = ws[lane];
        x = warp_incl_scan(x);
        ws[lane] = x;
    }
    __syncthreads();
    int excl = inc - v + (wid ? ws[wid - 1] : 0) + (b ? g_bsum[b - 1] : 0);
    if (i < N) { g_rowstart[i] = excl; g_cursor[i] = excl; }
}

__global__ __launch_bounds__(256) void gnn_scatter(
    const int* __restrict__ rows,
    const int* __restrict__ cols,
    const float* __restrict__ vals, int E)
{
    const int e = blockIdx.x * blockDim.x + threadIdx.x;
    if (e >= E) return;
    const int r   = __ldg(rows + e);
    const int pos = atomicAdd(&g_cursor[r], 1);
    g_edges[pos] = make_int2(__ldg(cols + e), __float_as_int(__ldg(vals + e)));
}

// ---------------------------------------------------------------------------
// CSR SpMM: 16 lanes per row, float4 per lane. (identical to R6)
// ---------------------------------------------------------------------------
__global__ __launch_bounds__(256) void gnn_spmm_csr(float* __restrict__ out, int N)
{
    const int gid = blockIdx.x * blockDim.x + threadIdx.x;
    const int row = gid >> 4;
    if (row >= N) return;
    const int lane16 = gid & 15;

    const int start = __ldg(g_rowstart + row);
    const int end   = __ldg(g_cursor + row);
    if (end <= start) return;

    const float4* __restrict__ Q4 = reinterpret_cast<const float4*>(g_Q);
    float4 acc = make_float4(0.f, 0.f, 0.f, 0.f);

    int j = start;
    for (; j + 3 < end; j += 4) {
        const int2 cv0 = __ldg(g_edges + j);
        const int2 cv1 = __ldg(g_edges + j + 1);
        const int2 cv2 = __ldg(g_edges + j + 2);
        const int2 cv3 = __ldg(g_edges + j + 3);
        const float4 q0 = __ldg(Q4 + (size_t)cv0.x * 16 + lane16);
        const float4 q1 = __ldg(Q4 + (size_t)cv1.x * 16 + lane16);
        const float4 q2 = __ldg(Q4 + (size_t)cv2.x * 16 + lane16);
        const float4 q3 = __ldg(Q4 + (size_t)cv3.x * 16 + lane16);
        const float v0 = __int_as_float(cv0.y);
        const float v1 = __int_as_float(cv1.y);
        const float v2 = __int_as_float(cv2.y);
        const float v3 = __int_as_float(cv3.y);
        acc.x = fmaf(v0, q0.x, acc.x); acc.y = fmaf(v0, q0.y, acc.y);
        acc.z = fmaf(v0, q0.z, acc.z); acc.w = fmaf(v0, q0.w, acc.w);
        acc.x = fmaf(v1, q1.x, acc.x); acc.y = fmaf(v1, q1.y, acc.y);
        acc.z = fmaf(v1, q1.z, acc.z); acc.w = fmaf(v1, q1.w, acc.w);
        acc.x = fmaf(v2, q2.x, acc.x); acc.y = fmaf(v2, q2.y, acc.y);
        acc.z = fmaf(v2, q2.z, acc.z); acc.w = fmaf(v2, q2.w, acc.w);
        acc.x = fmaf(v3, q3.x, acc.x); acc.y = fmaf(v3, q3.y, acc.y);
        acc.z = fmaf(v3, q3.z, acc.z); acc.w = fmaf(v3, q3.w, acc.w);
    }
    for (; j < end; ++j) {
        const int2 cv = __ldg(g_edges + j);
        const float4 q = __ldg(Q4 + (size_t)cv.x * 16 + lane16);
        const float v = __int_as_float(cv.y);
        acc.x = fmaf(v, q.x, acc.x); acc.y = fmaf(v, q.y, acc.y);
        acc.z = fmaf(v, q.z, acc.z); acc.w = fmaf(v, q.w, acc.w);
    }

    float4* orow = reinterpret_cast<float4*>(out) + (size_t)row * 16 + lane16;
    float4 o = *orow;
    o.x += acc.x; o.y += acc.y; o.z += acc.z; o.w += acc.w;
    *orow = o;
}

extern "C" void kernel_launch(void* const* d_in, const int* in_sizes, int n_in,
                              void* d_out, int out_size)
{
    const int*   rows = (const int*)  d_in[0];
    const int*   cols = (const int*)  d_in[1];
    const float* vals = (const float*)d_in[2];
    const float* X    = (const float*)d_in[3];
    const float* W1   = (const float*)d_in[4];
    const float* b1   = (const float*)d_in[5];
    const float* W2   = (const float*)d_in[6];
    const float* b2   = (const float*)d_in[7];
    float* out = (float*)d_out;

    const int E = in_sizes[0];
    const int N = in_sizes[3] / FDIM;

    cudaFuncSetAttribute(gnn_dense_hist, cudaFuncAttributeMaxDynamicSharedMemorySize, 49152);

    void* p = nullptr;
    cudaGetSymbolAddress(&p, g_cnt);
    cudaMemsetAsync(p, 0, (size_t)N * sizeof(int));

    const int blocksD = (N + 63) / 64;
    gnn_dense_hist<<<blocksD, 256, 49152>>>(X, W1, b1, W2, b2, rows, out, N, E);

    const int nb = (N + 1023) / 1024;
    scan_blocksums<<<nb, 1024>>>(N);
    scan_bsums<<<1, 128>>>(nb);
    scan_write<<<nb, 1024>>>(N);

    gnn_scatter<<<(E + 255) / 256, 256>>>(rows, cols, vals, E);

    const long long work = (long long)N * 16;
    gnn_spmm_csr<<<(int)((work + 255) / 256), 256>>>(out, N);
}